// round 10
// baseline (speedup 1.0000x reference)
#include <cuda_runtime.h>
#include <cstdint>
#include <cstddef>

// ============================================================================
// Problem dims
// ============================================================================
constexpr int NBR = 36;    // branches (IN_DIM)
constexpr int HID = 512;
constexpr int EMB = 1024;
constexpr int BATCH = 2048;
constexpr int NRNK = HID + 1;  // 513 rank buckets (0..512)

constexpr int SEGS = 8;            // rank segments
constexpr int RSEG = HID / SEGS;   // 64 ranks per segment
constexpr int DTH  = 256;          // threads per build block
constexpr int DCHUNKS = EMB / DTH; // 4 d-chunks

// ============================================================================
// Scratch (__device__ globals — no runtime allocation)
// ============================================================================
__device__ int   g_sidx [NBR * HID];   // original unit index, sorted-knee order
__device__ float g_dss  [NBR * HID];   // slope delta, sorted order
__device__ float g_dcs  [NBR * HID];   // intercept delta, sorted order
__device__ float g_slos [NBR * HID];   // base slope, sorted order
__device__ float g_clos [NBR * HID];   // base intercept, sorted order

// Batch items sorted by rank per branch: {b, float_bits(x)}
__device__ int2 g_items[NBR * BATCH];
// Rank bucket offsets per branch: 514 entries (exclusive prefix, [513]=2048)
__device__ int g_roff[NBR * (NRNK + 1)];

// Segment partial sums: [NBR][SEGS][EMB]
__device__ float g_Bsl[NBR * SEGS * EMB];
__device__ float g_Bsc[NBR * SEGS * EMB];
__device__ float g_Pds[NBR * SEGS * EMB];
__device__ float g_Pdc[NBR * SEGS * EMB];

// ============================================================================
// Kernel 1: knees + bitonic sort + batch rank counting-sort (36 blocks x 512)
//
// leaky(z) = z (z>=0) else 0.01 z,  z = W1*x + b1;  knee t = -b1/W1.
//  W1>0: below knee (0.01W1,0.01b1), above (W1,b1)   => ds=+0.99W1, dc=+0.99b1
//  W1<0: below (W1,b1), above (0.01W1,0.01b1)        => ds=-0.99W1, dc=-0.99b1
//  W1=0: constant; t=+inf, ds=dc=0
// out is continuous at each knee -> rank ties and bucket ordering are harmless.
// ============================================================================
__global__ void __launch_bounds__(HID)
prep_kernel(const float* __restrict__ W1, const float* __restrict__ b1,
            const float* __restrict__ x) {
    __shared__ float sk[HID];
    __shared__ int   sv[HID];
    __shared__ float sds[HID];
    __shared__ float sdc[HID];
    __shared__ float sslo[HID];
    __shared__ float sclo[HID];
    __shared__ int   hist[NRNK];
    __shared__ int   sbase[NRNK + 1];
    __shared__ int   scnt[NRNK];
    __shared__ int   wsum[16];

    const int i = blockIdx.x;
    const int j = threadIdx.x;
    const int lane = j & 31;
    const int wrp  = j >> 5;

    const float w = W1[i * HID + j];
    const float b = b1[i * HID + j];

    float t, slo, clo, ds, dc;
    if (w > 0.0f) {
        t = -b / w;
        slo = 0.01f * w; clo = 0.01f * b;
        ds = 0.99f * w;  dc = 0.99f * b;
    } else if (w < 0.0f) {
        t = -b / w;
        slo = w; clo = b;
        ds = -0.99f * w; dc = -0.99f * b;
    } else {
        t = __int_as_float(0x7f800000);  // +inf (never crossed)
        slo = 0.0f;
        clo = (b >= 0.0f) ? b : 0.01f * b;
        ds = 0.0f; dc = 0.0f;
    }

    sk[j] = t; sv[j] = j;
    sds[j] = ds; sdc[j] = dc;
    sslo[j] = slo; sclo[j] = clo;
    __syncthreads();

    // Bitonic sort ascending on sk, carrying sv
    for (int k = 2; k <= HID; k <<= 1) {
        for (int jj = k >> 1; jj > 0; jj >>= 1) {
            int ixj = j ^ jj;
            if (ixj > j) {
                bool up = ((j & k) == 0);
                float a = sk[j], c = sk[ixj];
                bool sw = up ? (a > c) : (a < c);
                if (sw) {
                    sk[j] = c; sk[ixj] = a;
                    int tv = sv[j]; sv[j] = sv[ixj]; sv[ixj] = tv;
                }
            }
            __syncthreads();
        }
    }

    const int src = sv[j];
    g_sidx [i * HID + j] = src;
    g_dss  [i * HID + j] = sds[src];
    g_dcs  [i * HID + j] = sdc[src];
    g_slos [i * HID + j] = sslo[src];
    g_clos [i * HID + j] = sclo[src];

    // ---- Counting sort of the 2048 batch items by rank ----
    for (int tt = j; tt < NRNK; tt += HID) hist[tt] = 0;
    __syncthreads();

    int   myrank[BATCH / HID];
    float myx[BATCH / HID];
#pragma unroll
    for (int q = 0; q < BATCH / HID; q++) {
        int bb = q * HID + j;
        float xv = x[(size_t)bb * NBR + i];
        int lo = 0, hi = HID;
        while (lo < hi) {
            int mid = (lo + hi) >> 1;
            if (sk[mid] <= xv) lo = mid + 1; else hi = mid;
        }
        myrank[q] = lo;
        myx[q] = xv;
        atomicAdd(&hist[lo], 1);
    }
    __syncthreads();

    // Exclusive prefix over bins 0..511 (512 threads), then bins 512/513
    {
        int v0 = hist[j];
        int inc = v0;
#pragma unroll
        for (int o = 1; o < 32; o <<= 1) {
            int n = __shfl_up_sync(0xFFFFFFFFu, inc, o);
            if (lane >= o) inc += n;
        }
        if (lane == 31) wsum[wrp] = inc;
        __syncthreads();
        if (wrp == 0) {
            int wv = (lane < 16) ? wsum[lane] : 0;
#pragma unroll
            for (int o = 1; o < 16; o <<= 1) {
                int n = __shfl_up_sync(0xFFFFFFFFu, wv, o);
                if (lane >= o) wv += n;
            }
            if (lane < 16) wsum[lane] = wv;  // inclusive warp sums
        }
        __syncthreads();
        int woff = (wrp == 0) ? 0 : wsum[wrp - 1];
        sbase[j] = woff + inc - v0;
        if (j == HID - 1) {
            int tot = woff + inc;
            sbase[HID] = tot;                      // bin 512 start
            sbase[HID + 1] = tot + hist[HID];      // = 2048
        }
    }
    __syncthreads();

    for (int tt = j; tt < NRNK; tt += HID) scnt[tt] = sbase[tt];
    __syncthreads();

#pragma unroll
    for (int q = 0; q < BATCH / HID; q++) {
        int bb = q * HID + j;
        int pos = atomicAdd(&scnt[myrank[q]], 1);
        g_items[i * BATCH + pos] = make_int2(bb, __float_as_int(myx[q]));
    }
    for (int tt = j; tt < NRNK + 1; tt += HID)
        g_roff[i * (NRNK + 1) + tt] = sbase[tt];
}

// ============================================================================
// Kernel 2: segment partial sums. grid (DCHUNKS, SEGS, NBR), DTH threads.
//   Bsl/Bsc: base partials; Pds/Pdc: delta partials over this segment's ranks.
// Proven-fast shape (R5): 1152 blocks, high occupancy, 64-deep chains.
// ============================================================================
__global__ void __launch_bounds__(DTH)
partial_kernel(const float* __restrict__ W2) {
    __shared__ int   six[RSEG];
    __shared__ float ssl[RSEG], scl[RSEG], sds[RSEG], sdc[RSEG];

    const int i = blockIdx.z;
    const int s = blockIdx.y;
    const int d = blockIdx.x * DTH + threadIdx.x;
    const int tid = threadIdx.x;

    if (tid < RSEG) {
        int r = s * RSEG + tid;
        six[tid] = g_sidx[i * HID + r];
        ssl[tid] = g_slos[i * HID + r];
        scl[tid] = g_clos[i * HID + r];
        sds[tid] = g_dss [i * HID + r];
        sdc[tid] = g_dcs [i * HID + r];
    }
    __syncthreads();

    const float* w2 = W2 + (size_t)i * HID * EMB + d;

    float bsl = 0.0f, bsc = 0.0f, pds = 0.0f, pdc = 0.0f;
#pragma unroll 8
    for (int k = 0; k < RSEG; k++) {
        float wv = __ldg(w2 + (size_t)six[k] * EMB);
        bsl = fmaf(ssl[k], wv, bsl);
        bsc = fmaf(scl[k], wv, bsc);
        pds = fmaf(sds[k], wv, pds);
        pdc = fmaf(sdc[k], wv, pdc);
    }

    const int o = (i * SEGS + s) * EMB + d;
    g_Bsl[o] = bsl;
    g_Bsc[o] = bsc;
    g_Pds[o] = pds;
    g_Pdc[o] = pdc;
}

// ============================================================================
// Kernel 3: prefix walk + DIRECT output scatter (no table, no spin).
// grid (DCHUNKS, SEGS, NBR), DTH threads.
//   start = b2 + sum_all B + sum_{s'<s} P  (fixed order -> deterministic)
//   for each rank k in segment: store out[b,i,d] = x_b*sl + sc for the rank's
//   pre-sorted batch items (coalesced 1KB per item), then apply delta via an
//   inline W2 column load (no register array -> no spills).
//   Last segment also handles rank 512 (above all knees).
// ============================================================================
__global__ void __launch_bounds__(DTH)
scatter_kernel(const float* __restrict__ W2, const float* __restrict__ b2,
               float* __restrict__ out) {
    __shared__ int   six[RSEG];
    __shared__ float sds[RSEG], sdc[RSEG];
    __shared__ int   roff[RSEG + 2];

    const int i = blockIdx.z;
    const int s = blockIdx.y;
    const int d = blockIdx.x * DTH + threadIdx.x;
    const int tid = threadIdx.x;
    const bool last = (s == SEGS - 1);

    if (tid < RSEG) {
        int r = s * RSEG + tid;
        six[tid] = g_sidx[i * HID + r];
        sds[tid] = g_dss [i * HID + r];
        sdc[tid] = g_dcs [i * HID + r];
    }
    {
        int cnt = last ? (RSEG + 2) : (RSEG + 1);
        int base = i * (NRNK + 1) + s * RSEG;
        for (int tt = tid; tt < cnt; tt += DTH)
            roff[tt] = g_roff[base + tt];
    }
    __syncthreads();

    // ---- Start offsets (fixed summation order -> deterministic) ----
    float sl = 0.0f;
    float sc = __ldg(b2 + i * EMB + d);
#pragma unroll
    for (int s2 = 0; s2 < SEGS; s2++) {
        int oo = (i * SEGS + s2) * EMB + d;
        sl += __ldg(g_Bsl + oo);
        sc += __ldg(g_Bsc + oo);
    }
#pragma unroll
    for (int s2 = 0; s2 < SEGS - 1; s2++) {
        if (s2 < s) {
            int oo = (i * SEGS + s2) * EMB + d;
            sl += __ldg(g_Pds + oo);
            sc += __ldg(g_Pdc + oo);
        }
    }

    // ---- Prefix walk + scatter ----
    const float* w2 = W2 + (size_t)i * HID * EMB + d;
    const int2* items = g_items + i * BATCH;

#pragma unroll 1
    for (int k = 0; k < RSEG; k++) {
        // Issue the delta's W2 load early; it's independent of the item stores.
        float wv = __ldg(w2 + (size_t)six[k] * EMB);
        const int p0 = roff[k], p1 = roff[k + 1];
        for (int p = p0; p < p1; p++) {
            int2 it = __ldg(items + p);           // broadcast: same addr all lanes
            float xv = __int_as_float(it.y);
            __stcs(out + ((size_t)it.x * NBR + i) * EMB + d,
                   fmaf(xv, sl, sc));
        }
        sl = fmaf(sds[k], wv, sl);
        sc = fmaf(sdc[k], wv, sc);
    }
    if (last) {  // rank 512: above all knees
        const int p0 = roff[RSEG], p1 = roff[RSEG + 1];
        for (int p = p0; p < p1; p++) {
            int2 it = __ldg(items + p);
            float xv = __int_as_float(it.y);
            __stcs(out + ((size_t)it.x * NBR + i) * EMB + d,
                   fmaf(xv, sl, sc));
        }
    }
}

// ============================================================================
// Launch
// ============================================================================
extern "C" void kernel_launch(void* const* d_in, const int* in_sizes, int n_in,
                              void* d_out, int out_size) {
    const float* x  = (const float*)d_in[0];
    const float* W1 = (const float*)d_in[1];
    const float* b1 = (const float*)d_in[2];
    const float* W2 = (const float*)d_in[3];
    const float* b2 = (const float*)d_in[4];
    float* out = (float*)d_out;

    prep_kernel<<<NBR, HID>>>(W1, b1, x);
    partial_kernel<<<dim3(DCHUNKS, SEGS, NBR), DTH>>>(W2);
    scatter_kernel<<<dim3(DCHUNKS, SEGS, NBR), DTH>>>(W2, b2, out);
}